// round 1
// baseline (speedup 1.0000x reference)
#include <cuda_runtime.h>

#define NN 50000
#define EE 800000
#define DIN 256
#define DH 128
#define NL 1000

// ---------------- scratch (no allocation allowed) ----------------
__device__ float g_h[NN * DH];
__device__ float g_res[NN * DH];
__device__ float g_agg[NN * DH];
__device__ int   g_rowptr[NN + 1];
__device__ int   g_cursor[NN + 1];
__device__ int   g_col[EE];
__device__ float g_wself[EE];
__device__ float g_wppi[EE];

// ---------------- CSR build ----------------
__global__ void zero_deg_kernel() {
    int i = blockIdx.x * blockDim.x + threadIdx.x;
    if (i <= NN) g_cursor[i] = 0;
}

__global__ void hist_kernel(const int* __restrict__ dst) {
    int e = blockIdx.x * blockDim.x + threadIdx.x;
    if (e < EE) atomicAdd(&g_cursor[dst[e]], 1);
}

// single-block inclusive scan of degrees -> row_ptr (exclusive form)
__global__ void scan_kernel() {
    __shared__ int sh[1024];
    __shared__ int carry;
    int tid = threadIdx.x;
    if (tid == 0) { carry = 0; g_rowptr[0] = 0; }
    __syncthreads();
    for (int base = 0; base < NN; base += 1024) {
        int i = base + tid;
        int v = (i < NN) ? g_cursor[i] : 0;
        sh[tid] = v;
        __syncthreads();
        #pragma unroll
        for (int off = 1; off < 1024; off <<= 1) {
            int t = (tid >= off) ? sh[tid - off] : 0;
            __syncthreads();
            sh[tid] += t;
            __syncthreads();
        }
        if (i < NN) g_rowptr[i + 1] = carry + sh[tid];
        __syncthreads();
        if (tid == 1023) carry += sh[1023];
        __syncthreads();
    }
}

__global__ void copy_cursor_kernel() {
    int i = blockIdx.x * blockDim.x + threadIdx.x;
    if (i <= NN) g_cursor[i] = g_rowptr[i];
}

__global__ void fill_kernel(const int* __restrict__ src, const int* __restrict__ dst,
                            const float* __restrict__ sw, const float* __restrict__ pw) {
    int e = blockIdx.x * blockDim.x + threadIdx.x;
    if (e < EE) {
        int p = atomicAdd(&g_cursor[dst[e]], 1);
        g_col[p]   = src[e];
        g_wself[p] = sw[e];
        g_wppi[p]  = pw[e];
    }
}

// ---------------- aggregation: warp per dst node, float4 lanes ----------------
__global__ __launch_bounds__(256) void aggregate_kernel(const float* __restrict__ h,
                                                        float* __restrict__ res,
                                                        float* __restrict__ agg) {
    int warp = (blockIdx.x * blockDim.x + threadIdx.x) >> 5;
    int lane = threadIdx.x & 31;
    if (warp >= NN) return;
    int beg = g_rowptr[warp];
    int end = g_rowptr[warp + 1];
    float4 as = make_float4(0.f, 0.f, 0.f, 0.f);
    float4 ap = make_float4(0.f, 0.f, 0.f, 0.f);
    const float4* __restrict__ h4 = (const float4*)h;
    for (int i = beg; i < end; i++) {
        int   s  = g_col[i];
        float ws = g_wself[i];
        float wp = g_wppi[i];
        float4 v = __ldg(&h4[s * 32 + lane]);
        as.x += ws * v.x; as.y += ws * v.y; as.z += ws * v.z; as.w += ws * v.w;
        ap.x += wp * v.x; ap.y += wp * v.y; ap.z += wp * v.z; ap.w += wp * v.w;
    }
    ((float4*)res)[warp * 32 + lane] = as;
    ((float4*)agg)[warp * 32 + lane] = ap;
}

// ---------------- tiled SGEMM with fused epilogue ----------------
// MODE 0: C = A@B + bias
// MODE 1: C = relu(A@B + bias)
// MODE 2: C = relu(A@B + bias) + resid
template <int MODE>
__global__ __launch_bounds__(256) void sgemm_kernel(
    int M, int N, int K,
    const float* __restrict__ A, const float* __restrict__ B,
    const float* __restrict__ bias, const float* __restrict__ resid,
    float* __restrict__ C)
{
    const int BM = 64, BN = 64, BK = 16;
    __shared__ float As[BK][BM];
    __shared__ float Bs[BK][BN];

    int tid = threadIdx.x;
    int tx = tid % 16;       // col group
    int ty = tid / 16;       // row group
    int bm = blockIdx.x * BM;
    int bn = blockIdx.y * BN;

    float acc[4][4];
    #pragma unroll
    for (int i = 0; i < 4; i++)
        #pragma unroll
        for (int j = 0; j < 4; j++) acc[i][j] = 0.f;

    int arow  = tid >> 2;          // 0..63
    int acol4 = (tid & 3) * 4;     // 0,4,8,12
    int brow  = tid >> 4;          // 0..15
    int bcol4 = (tid & 15) * 4;    // 0..60

    for (int k0 = 0; k0 < K; k0 += BK) {
        // load A tile (BM x BK), transposed into As[k][m]
        float4 av = make_float4(0.f, 0.f, 0.f, 0.f);
        if (bm + arow < M)
            av = *(const float4*)&A[(size_t)(bm + arow) * K + k0 + acol4];
        As[acol4 + 0][arow] = av.x;
        As[acol4 + 1][arow] = av.y;
        As[acol4 + 2][arow] = av.z;
        As[acol4 + 3][arow] = av.w;

        // load B tile (BK x BN)
        float4 bv = make_float4(0.f, 0.f, 0.f, 0.f);
        if (bn + bcol4 < N)   // N % 4 == 0 in all uses
            bv = *(const float4*)&B[(size_t)(k0 + brow) * N + bn + bcol4];
        *(float4*)&Bs[brow][bcol4] = bv;

        __syncthreads();

        #pragma unroll
        for (int k = 0; k < BK; k++) {
            float4 ra = *(const float4*)&As[k][ty * 4];
            float4 rb = *(const float4*)&Bs[k][tx * 4];
            float a_[4] = {ra.x, ra.y, ra.z, ra.w};
            float b_[4] = {rb.x, rb.y, rb.z, rb.w};
            #pragma unroll
            for (int i = 0; i < 4; i++)
                #pragma unroll
                for (int j = 0; j < 4; j++)
                    acc[i][j] += a_[i] * b_[j];
        }
        __syncthreads();
    }

    #pragma unroll
    for (int i = 0; i < 4; i++) {
        int r = bm + ty * 4 + i;
        if (r >= M) continue;
        #pragma unroll
        for (int j = 0; j < 4; j++) {
            int c = bn + tx * 4 + j;
            if (c >= N) continue;
            float v = acc[i][j] + bias[c];
            if (MODE >= 1) v = fmaxf(v, 0.f);
            if (MODE == 2) v += resid[(size_t)r * N + c];
            C[(size_t)r * N + c] = v;
        }
    }
}

// ---------------- driver ----------------
extern "C" void kernel_launch(void* const* d_in, const int* in_sizes, int n_in,
                              void* d_out, int out_size) {
    const float* x      = (const float*)d_in[0];
    const int*   src    = (const int*)  d_in[1];
    const int*   dst    = (const int*)  d_in[2];
    const float* self_w = (const float*)d_in[3];
    const float* ppi_w  = (const float*)d_in[4];
    const float* W_in   = (const float*)d_in[5];
    const float* b_in   = (const float*)d_in[6];
    const float* W1     = (const float*)d_in[7];
    const float* b1     = (const float*)d_in[8];
    const float* W2     = (const float*)d_in[9];
    const float* b2     = (const float*)d_in[10];
    const float* W_out  = (const float*)d_in[11];
    const float* b_out  = (const float*)d_in[12];
    float* out = (float*)d_out;

    float* h   = nullptr; cudaGetSymbolAddress((void**)&h,   g_h);
    float* res = nullptr; cudaGetSymbolAddress((void**)&res, g_res);
    float* agg = nullptr; cudaGetSymbolAddress((void**)&agg, g_agg);

    // build CSR (deterministic work each call)
    zero_deg_kernel<<<(NN + 256) / 256, 256>>>();
    hist_kernel<<<(EE + 255) / 256, 256>>>(dst);
    scan_kernel<<<1, 1024>>>();
    copy_cursor_kernel<<<(NN + 256) / 256, 256>>>();
    fill_kernel<<<(EE + 255) / 256, 256>>>(src, dst, self_w, ppi_w);

    // h = relu(x @ W_in + b_in)
    {
        dim3 grid((NN + 63) / 64, (DH + 63) / 64);
        sgemm_kernel<1><<<grid, 256>>>(NN, DH, DIN, x, W_in, b_in, nullptr, h);
    }

    // two GCN layers
    {
        dim3 grid((NN + 63) / 64, (DH + 63) / 64);
        int agg_blocks = (NN * 32 + 255) / 256;

        aggregate_kernel<<<agg_blocks, 256>>>(h, res, agg);
        sgemm_kernel<2><<<grid, 256>>>(NN, DH, DH, agg, W1, b1, res, h);

        aggregate_kernel<<<agg_blocks, 256>>>(h, res, agg);
        sgemm_kernel<2><<<grid, 256>>>(NN, DH, DH, agg, W2, b2, res, h);
    }

    // out = h @ W_out + b_out
    {
        dim3 grid((NN + 63) / 64, (NL + 63) / 64);
        sgemm_kernel<0><<<grid, 256>>>(NN, NL, DH, h, W_out, b_out, nullptr, out);
    }
}

// round 7
// speedup vs baseline: 1.5383x; 1.5383x over previous
#include <cuda_runtime.h>
#include <cstdint>

#define NN 50000
#define EE 800000
#define DIN 256
#define DH 128
#define NL 1000
#define NB_SCAN ((NN + 1023) / 1024)

// ---------------- scratch (no allocation allowed) ----------------
__device__ float g_h[NN * DH];
__device__ float g_res[NN * DH];
__device__ float g_agg[NN * DH];
__device__ int   g_rowptr[NN + 1];
__device__ int   g_cursor[NN + 1];
__device__ int   g_col[EE];
__device__ float g_wself[EE];
__device__ float g_wppi[EE];
__device__ int   g_blocksum[64];
__device__ int   g_blockoff[64];
__device__ float g_wtin[DH * DIN];     // [128][256]
__device__ float g_wt1[DH * DH];
__device__ float g_wt2[DH * DH];
__device__ float g_wtout[NL * DH];     // [1000][128]

// ---------------- CSR build ----------------
__global__ void zero_deg_kernel() {
    int i = blockIdx.x * blockDim.x + threadIdx.x;
    if (i <= NN) g_cursor[i] = 0;
}

__global__ void hist_kernel(const int* __restrict__ dst) {
    int e = blockIdx.x * blockDim.x + threadIdx.x;
    if (e < EE) atomicAdd(&g_cursor[dst[e]], 1);
}

__global__ __launch_bounds__(1024) void scan_block_kernel() {
    int tid = threadIdx.x, b = blockIdx.x;
    int i = b * 1024 + tid;
    int v = (i < NN) ? g_cursor[i] : 0;
    int lane = tid & 31, w = tid >> 5;
    int x = v;
    #pragma unroll
    for (int o = 1; o < 32; o <<= 1) {
        int t = __shfl_up_sync(0xffffffffu, x, o);
        if (lane >= o) x += t;
    }
    __shared__ int ws[32];
    if (lane == 31) ws[w] = x;
    __syncthreads();
    if (w == 0) {
        int y = ws[lane];
        #pragma unroll
        for (int o = 1; o < 32; o <<= 1) {
            int t = __shfl_up_sync(0xffffffffu, y, o);
            if (lane >= o) y += t;
        }
        ws[lane] = y;
    }
    __syncthreads();
    int incl = x + (w ? ws[w - 1] : 0);
    if (i < NN) g_cursor[i] = incl;
    if (tid == 1023) g_blocksum[b] = incl;
}

__global__ void scan_sums_kernel() {
    int tid = threadIdx.x;   // 64 threads
    int v = (tid < NB_SCAN) ? g_blocksum[tid] : 0;
    int lane = tid & 31, w = tid >> 5;
    int x = v;
    #pragma unroll
    for (int o = 1; o < 32; o <<= 1) {
        int t = __shfl_up_sync(0xffffffffu, x, o);
        if (lane >= o) x += t;
    }
    __shared__ int ws[2];
    if (lane == 31) ws[w] = x;
    __syncthreads();
    int excl = x - v + ((w == 1) ? ws[0] : 0);
    if (tid < NB_SCAN) g_blockoff[tid] = excl;
}

__global__ void finalize_kernel() {
    int i = blockIdx.x * blockDim.x + threadIdx.x;
    if (i < NN) g_rowptr[i + 1] = g_cursor[i] + g_blockoff[i >> 10];
    if (i == 0) g_rowptr[0] = 0;
}

__global__ void copy_cursor_kernel() {
    int i = blockIdx.x * blockDim.x + threadIdx.x;
    if (i <= NN) g_cursor[i] = g_rowptr[i];
}

__global__ void fill_kernel(const int* __restrict__ src, const int* __restrict__ dst,
                            const float* __restrict__ sw, const float* __restrict__ pw) {
    int e = blockIdx.x * blockDim.x + threadIdx.x;
    if (e < EE) {
        int p = atomicAdd(&g_cursor[dst[e]], 1);
        g_col[p]   = src[e];
        g_wself[p] = sw[e];
        g_wppi[p]  = pw[e];
    }
}

// ---------------- weight transpose: W[K][N] -> Wt[N][K] ----------------
__global__ void transpose_kernel(const float* __restrict__ W, float* __restrict__ Wt,
                                 int K, int N) {
    __shared__ float t[32][33];
    int kb = blockIdx.y * 32, nb = blockIdx.x * 32;
    int tx = threadIdx.x, ty = threadIdx.y;   // 32 x 8
    #pragma unroll
    for (int r = ty; r < 32; r += 8) {
        int k = kb + r, n = nb + tx;
        t[r][tx] = (k < K && n < N) ? W[(size_t)k * N + n] : 0.f;
    }
    __syncthreads();
    #pragma unroll
    for (int r = ty; r < 32; r += 8) {
        int n = nb + r, k = kb + tx;
        if (n < N && k < K) Wt[(size_t)n * K + k] = t[tx][r];
    }
}

// ---------------- aggregation: warp per dst node, float4 lanes ----------------
__global__ __launch_bounds__(256) void aggregate_kernel(const float* __restrict__ h,
                                                        float* __restrict__ res,
                                                        float* __restrict__ agg) {
    int warp = (blockIdx.x * blockDim.x + threadIdx.x) >> 5;
    int lane = threadIdx.x & 31;
    if (warp >= NN) return;
    int beg = g_rowptr[warp];
    int end = g_rowptr[warp + 1];
    float4 as = make_float4(0.f, 0.f, 0.f, 0.f);
    float4 ap = make_float4(0.f, 0.f, 0.f, 0.f);
    const float4* __restrict__ h4 = (const float4*)h;
    for (int i = beg; i < end; i++) {
        int   s  = g_col[i];
        float ws = g_wself[i];
        float wp = g_wppi[i];
        float4 v = __ldg(&h4[s * 32 + lane]);
        as.x += ws * v.x; as.y += ws * v.y; as.z += ws * v.z; as.w += ws * v.w;
        ap.x += wp * v.x; ap.y += wp * v.y; ap.z += wp * v.z; ap.w += wp * v.w;
    }
    ((float4*)res)[warp * 32 + lane] = as;
    ((float4*)agg)[warp * 32 + lane] = ap;
}

// ---------------- 3xTF32 mma.sync GEMM: C[M,N] = A[M,K] @ Bt[N,K]^T ----------------
// fp32-accuracy via hi/lo split: a*b ~= ah*bh + ah*bl + al*bh
// mode 0: +bias; mode 1: relu(+bias); mode 2: relu(+bias)+resid
// Block tile 128x128x32, 8 warps (4x2), warp tile 32x64 of m16n8k8 frags.
__device__ __forceinline__ void mma_tf32_16x8x8(float* d, const uint32_t* a, const uint32_t* b) {
    asm volatile(
        "mma.sync.aligned.m16n8k8.row.col.f32.tf32.tf32.f32 "
        "{%0,%1,%2,%3}, {%4,%5,%6,%7}, {%8,%9}, {%0,%1,%2,%3};"
        : "+f"(d[0]), "+f"(d[1]), "+f"(d[2]), "+f"(d[3])
        : "r"(a[0]), "r"(a[1]), "r"(a[2]), "r"(a[3]), "r"(b[0]), "r"(b[1]));
}

__device__ __forceinline__ uint32_t to_tf32(float f) {
    uint32_t r;
    asm("cvt.rna.tf32.f32 %0, %1;" : "=r"(r) : "f"(f));
    return r;
}

__device__ __forceinline__ void split_tf32(float f, uint32_t& hi, uint32_t& lo) {
    hi = to_tf32(f);
    lo = to_tf32(f - __uint_as_float(hi));
}

__global__ __launch_bounds__(256, 2) void gemm_tf32_kernel(
    int M, int N, int K,
    const float* __restrict__ A, const float* __restrict__ Bt,
    const float* __restrict__ bias, const float* __restrict__ resid,
    float* __restrict__ C, int mode)
{
    const int BK = 32;
    __shared__ float sA[128][BK + 4];
    __shared__ float sB[128][BK + 4];

    int tid = threadIdx.x;
    int wid = tid >> 5;
    int lane = tid & 31;
    int gid = lane >> 2;      // group id 0..7
    int tig = lane & 3;       // thread in group 0..3
    int wm = (wid >> 1) * 32; // warp m offset 0/32/64/96
    int wn = (wid & 1) * 64;  // warp n offset 0/64
    int m0 = blockIdx.x * 128;
    int n0 = blockIdx.y * 128;

    float acc[2][8][4];
    #pragma unroll
    for (int mf = 0; mf < 2; mf++)
        #pragma unroll
        for (int nf = 0; nf < 8; nf++)
            #pragma unroll
            for (int q = 0; q < 4; q++) acc[mf][nf][q] = 0.f;

    for (int k0 = 0; k0 < K; k0 += BK) {
        // global -> shared: 4 float4 per thread per tile
        #pragma unroll
        for (int i = 0; i < 4; i++) {
            int f = tid + i * 256;
            int row = f >> 3;
            int kq = (f & 7) * 4;
            float4 va = make_float4(0.f, 0.f, 0.f, 0.f);
            if (m0 + row < M) va = *(const float4*)(A + (size_t)(m0 + row) * K + k0 + kq);
            *(float4*)&sA[row][kq] = va;
            float4 vb = make_float4(0.f, 0.f, 0.f, 0.f);
            if (n0 + row < N) vb = *(const float4*)(Bt + (size_t)(n0 + row) * K + k0 + kq);
            *(float4*)&sB[row][kq] = vb;
        }
        __syncthreads();

        #pragma unroll
        for (int ks = 0; ks < 4; ks++) {
            int kk = ks * 8;
            uint32_t ah[2][4], al[2][4];
            #pragma unroll
            for (int mf = 0; mf < 2; mf++) {
                int r = wm + mf * 16 + gid;
                split_tf32(sA[r][kk + tig],         ah[mf][0], al[mf][0]);
                split_tf32(sA[r + 8][kk + tig],     ah[mf][1], al[mf][1]);
                split_tf32(sA[r][kk + tig + 4],     ah[mf][2], al[mf][2]);
                split_tf32(sA[r + 8][kk + tig + 4], ah[mf][3], al[mf][3]);
            }
            #pragma unroll
            for (int nf = 0; nf < 8; nf++) {
                int c = wn + nf * 8 + gid;
                uint32_t bh[2], bl[2];
                split_tf32(sB[c][kk + tig],     bh[0], bl[0]);
                split_tf32(sB[c][kk + tig + 4], bh[1], bl[1]);
                #pragma unroll
                for (int mf = 0; mf < 2; mf++) {
                    mma_tf32_16x8x8(acc[mf][nf], al[mf], bh);
                    mma_tf32_16x8x8(acc[mf][nf], ah[mf], bl);
                    mma_tf32_16x8x8(acc[mf][nf], ah[mf], bh);
                }
            }
        }
        __syncthreads();
    }

    // epilogue
    #pragma unroll
    for (int mf = 0; mf < 2; mf++) {
        int r0 = m0 + wm + mf * 16 + gid;
        int r1 = r0 + 8;
        #pragma unroll
        for (int nf = 0; nf < 8; nf++) {
            int c = n0 + wn + nf * 8 + 2 * tig;
            if (c >= N) continue;
            float bv0 = bias[c];
            float bv1 = bias[c + 1];
            float v00 = acc[mf][nf][0] + bv0;
            float v01 = acc[mf][nf][1] + bv1;
            float v10 = acc[mf][nf][2] + bv0;
            float v11 = acc[mf][nf][3] + bv1;
            if (mode >= 1) {
                v00 = fmaxf(v00, 0.f); v01 = fmaxf(v01, 0.f);
                v10 = fmaxf(v10, 0.f); v11 = fmaxf(v11, 0.f);
            }
            if (r0 < M) {
                if (mode == 2) {
                    v00 += resid[(size_t)r0 * N + c];
                    v01 += resid[(size_t)r0 * N + c + 1];
                }
                *(float2*)(C + (size_t)r0 * N + c) = make_float2(v00, v01);
            }
            if (r1 < M) {
                if (mode == 2) {
                    v10 += resid[(size_t)r1 * N + c];
                    v11 += resid[(size_t)r1 * N + c + 1];
                }
                *(float2*)(C + (size_t)r1 * N + c) = make_float2(v10, v11);
            }
        }
    }
}

// ---------------- driver ----------------
extern "C" void kernel_launch(void* const* d_in, const int* in_sizes, int n_in,
                              void* d_out, int out_size) {
    const float* x      = (const float*)d_in[0];
    const int*   src    = (const int*)  d_in[1];
    const int*   dst    = (const int*)  d_in[2];
    const float* self_w = (const float*)d_in[3];
    const float* ppi_w  = (const float*)d_in[4];
    const float* W_in   = (const float*)d_in[5];
    const float* b_in   = (const float*)d_in[6];
    const float* W1     = (const float*)d_in[7];
    const float* b1     = (const float*)d_in[8];
    const float* W2     = (const float*)d_in[9];
    const float* b2     = (const float*)d_in[10];
    const float* W_out  = (const float*)d_in[11];
    const float* b_out  = (const float*)d_in[12];
    float* out = (float*)d_out;

    float* h     = nullptr; cudaGetSymbolAddress((void**)&h,     g_h);
    float* res   = nullptr; cudaGetSymbolAddress((void**)&res,   g_res);
    float* agg   = nullptr; cudaGetSymbolAddress((void**)&agg,   g_agg);
    float* wtin  = nullptr; cudaGetSymbolAddress((void**)&wtin,  g_wtin);
    float* wt1   = nullptr; cudaGetSymbolAddress((void**)&wt1,   g_wt1);
    float* wt2   = nullptr; cudaGetSymbolAddress((void**)&wt2,   g_wt2);
    float* wtout = nullptr; cudaGetSymbolAddress((void**)&wtout, g_wtout);

    // CSR build
    zero_deg_kernel<<<(NN + 256) / 256, 256>>>();
    hist_kernel<<<(EE + 255) / 256, 256>>>(dst);
    scan_block_kernel<<<NB_SCAN, 1024>>>();
    scan_sums_kernel<<<1, 64>>>();
    finalize_kernel<<<(NN + 255) / 256, 256>>>();
    copy_cursor_kernel<<<(NN + 256) / 256, 256>>>();
    fill_kernel<<<(EE + 255) / 256, 256>>>(src, dst, self_w, ppi_w);

    // weight transposes: W[K][N] -> Wt[N][K]
    {
        dim3 blk(32, 8);
        transpose_kernel<<<dim3((DH + 31) / 32, (DIN + 31) / 32), blk>>>(W_in,  wtin,  DIN, DH);
        transpose_kernel<<<dim3((DH + 31) / 32, (DH + 31) / 32),  blk>>>(W1,    wt1,   DH,  DH);
        transpose_kernel<<<dim3((DH + 31) / 32, (DH + 31) / 32),  blk>>>(W2,    wt2,   DH,  DH);
        transpose_kernel<<<dim3((NL + 31) / 32, (DH + 31) / 32),  blk>>>(W_out, wtout, DH,  NL);
    }

    int mtiles = (NN + 127) / 128;   // 391

    // h = relu(x @ W_in + b_in)
    gemm_tf32_kernel<<<dim3(mtiles, 1), 256>>>(NN, DH, DIN, x, wtin, b_in, nullptr, h, 1);

    // two GCN layers
    int agg_blocks = (NN * 32 + 255) / 256;
    aggregate_kernel<<<agg_blocks, 256>>>(h, res, agg);
    gemm_tf32_kernel<<<dim3(mtiles, 1), 256>>>(NN, DH, DH, agg, wt1, b1, res, h, 2);
    aggregate_kernel<<<agg_blocks, 256>>>(h, res, agg);
    gemm_tf32_kernel<<<dim3(mtiles, 1), 256>>>(NN, DH, DH, agg, wt2, b2, res, h, 2);

    // out = h @ W_out + b_out
    gemm_tf32_kernel<<<dim3(mtiles, (NL + 127) / 128), 256>>>(NN, NL, DH, h, wtout, b_out, nullptr, out, 0);
}

// round 9
// speedup vs baseline: 1.8921x; 1.2300x over previous
#include <cuda_runtime.h>
#include <cstdint>

#define NN 50000
#define EE 800000
#define DIN 256
#define DH 128
#define NL 1000
#define NB_SCAN ((NN + 1023) / 1024)

// ---------------- scratch (no allocation allowed) ----------------
__device__ float g_h[NN * DH];
__device__ float g_res[NN * DH];
__device__ float g_agg[NN * DH];
__device__ int   g_rowptr[NN + 1];
__device__ int   g_cursor[NN + 1];
__device__ int   g_col[EE];
__device__ float g_wself[EE];
__device__ float g_wppi[EE];
__device__ int   g_blocksum[64];
__device__ int   g_blockoff[64];
__device__ float g_wtin[DH * DIN];     // [128][256]
__device__ float g_wt1[DH * DH];
__device__ float g_wt2[DH * DH];
__device__ float g_wtout[NL * DH];     // [1000][128]

// ---------------- CSR build ----------------
__global__ void zero_deg_kernel() {
    int i = blockIdx.x * blockDim.x + threadIdx.x;
    if (i <= NN) g_cursor[i] = 0;
}

__global__ void hist_kernel(const int* __restrict__ dst) {
    int e = blockIdx.x * blockDim.x + threadIdx.x;
    if (e < EE) atomicAdd(&g_cursor[dst[e]], 1);
}

__global__ __launch_bounds__(1024) void scan_block_kernel() {
    int tid = threadIdx.x, b = blockIdx.x;
    int i = b * 1024 + tid;
    int v = (i < NN) ? g_cursor[i] : 0;
    int lane = tid & 31, w = tid >> 5;
    int x = v;
    #pragma unroll
    for (int o = 1; o < 32; o <<= 1) {
        int t = __shfl_up_sync(0xffffffffu, x, o);
        if (lane >= o) x += t;
    }
    __shared__ int ws[32];
    if (lane == 31) ws[w] = x;
    __syncthreads();
    if (w == 0) {
        int y = ws[lane];
        #pragma unroll
        for (int o = 1; o < 32; o <<= 1) {
            int t = __shfl_up_sync(0xffffffffu, y, o);
            if (lane >= o) y += t;
        }
        ws[lane] = y;
    }
    __syncthreads();
    int incl = x + (w ? ws[w - 1] : 0);
    if (i < NN) g_cursor[i] = incl;
    if (tid == 1023) g_blocksum[b] = incl;
}

__global__ void scan_sums_kernel() {
    int tid = threadIdx.x;   // 64 threads
    int v = (tid < NB_SCAN) ? g_blocksum[tid] : 0;
    int lane = tid & 31, w = tid >> 5;
    int x = v;
    #pragma unroll
    for (int o = 1; o < 32; o <<= 1) {
        int t = __shfl_up_sync(0xffffffffu, x, o);
        if (lane >= o) x += t;
    }
    __shared__ int ws[2];
    if (lane == 31) ws[w] = x;
    __syncthreads();
    int excl = x - v + ((w == 1) ? ws[0] : 0);
    if (tid < NB_SCAN) g_blockoff[tid] = excl;
}

// writes rowptr AND primes cursor (cursor[i] = rowptr[i]) in one pass
__global__ void finalize_kernel() {
    int i = blockIdx.x * blockDim.x + threadIdx.x;
    if (i < NN) {
        int v = g_cursor[i] + g_blockoff[i >> 10];
        g_rowptr[i + 1] = v;
    }
    if (i == 0) g_rowptr[0] = 0;
}

__global__ void prime_cursor_kernel() {
    int i = blockIdx.x * blockDim.x + threadIdx.x;
    if (i <= NN) g_cursor[i] = g_rowptr[i];
}

__global__ void fill_kernel(const int* __restrict__ src, const int* __restrict__ dst,
                            const float* __restrict__ sw, const float* __restrict__ pw) {
    int e = blockIdx.x * blockDim.x + threadIdx.x;
    if (e < EE) {
        int p = atomicAdd(&g_cursor[dst[e]], 1);
        g_col[p]   = src[e];
        g_wself[p] = sw[e];
        g_wppi[p]  = pw[e];
    }
}

// ---------------- weight transpose: W[K][N] -> Wt[N][K] ----------------
__global__ void transpose_kernel(const float* __restrict__ W, float* __restrict__ Wt,
                                 int K, int N) {
    __shared__ float t[32][33];
    int kb = blockIdx.y * 32, nb = blockIdx.x * 32;
    int tx = threadIdx.x, ty = threadIdx.y;   // 32 x 8
    #pragma unroll
    for (int r = ty; r < 32; r += 8) {
        int k = kb + r, n = nb + tx;
        t[r][tx] = (k < K && n < N) ? W[(size_t)k * N + n] : 0.f;
    }
    __syncthreads();
    #pragma unroll
    for (int r = ty; r < 32; r += 8) {
        int n = nb + r, k = kb + tx;
        if (n < N && k < K) Wt[(size_t)n * K + k] = t[tx][r];
    }
}

// ---------------- aggregation: warp per dst node, float4 lanes ----------------
__global__ __launch_bounds__(256) void aggregate_kernel(const float* __restrict__ h,
                                                        float* __restrict__ res,
                                                        float* __restrict__ agg) {
    int warp = (blockIdx.x * blockDim.x + threadIdx.x) >> 5;
    int lane = threadIdx.x & 31;
    if (warp >= NN) return;
    int beg = g_rowptr[warp];
    int end = g_rowptr[warp + 1];
    float4 as = make_float4(0.f, 0.f, 0.f, 0.f);
    float4 ap = make_float4(0.f, 0.f, 0.f, 0.f);
    const float4* __restrict__ h4 = (const float4*)h;
    for (int i = beg; i < end; i++) {
        int   s  = g_col[i];
        float ws = g_wself[i];
        float wp = g_wppi[i];
        float4 v = __ldg(&h4[s * 32 + lane]);
        as.x += ws * v.x; as.y += ws * v.y; as.z += ws * v.z; as.w += ws * v.w;
        ap.x += wp * v.x; ap.y += wp * v.y; ap.z += wp * v.z; ap.w += wp * v.w;
    }
    ((float4*)res)[warp * 32 + lane] = as;
    ((float4*)agg)[warp * 32 + lane] = ap;
}

// ---------------- bf16x2-split mma.sync GEMM: C[M,N] = A[M,K] @ Bt[N,K]^T ----------------
// fp32-near accuracy: a = ah + al (ah = fp32 truncated to bf16 => al exact),
// a*b ~= ah*bh + ah*bl + al*bh  (dropped al*bl ~ 2^-16)
// mode 0: +bias; mode 1: relu(+bias); mode 2: relu(+bias)+resid
// Block tile 128x128x32, 8 warps (4x2), warp tile 32x64 of m16n8k16 frags.
__device__ __forceinline__ void mma_bf16(float* d, const uint32_t* a, const uint32_t* b) {
    asm volatile(
        "mma.sync.aligned.m16n8k16.row.col.f32.bf16.bf16.f32 "
        "{%0,%1,%2,%3}, {%4,%5,%6,%7}, {%8,%9}, {%0,%1,%2,%3};"
        : "+f"(d[0]), "+f"(d[1]), "+f"(d[2]), "+f"(d[3])
        : "r"(a[0]), "r"(a[1]), "r"(a[2]), "r"(a[3]), "r"(b[0]), "r"(b[1]));
}

// split two consecutive fp32 (x=k even, y=k+1) into packed bf16x2 hi and lo.
// hi: truncated top-16 bits (exact split); lo: rounded bf16 of exact residual.
__device__ __forceinline__ void split2_bf16(float x, float y, uint32_t& hi, uint32_t& lo) {
    uint32_t xb = __float_as_uint(x), yb = __float_as_uint(y);
    hi = __byte_perm(xb, yb, 0x7632);                 // {lo16=x[31:16], hi16=y[31:16]}
    float xl = x - __uint_as_float(xb & 0xffff0000u); // exact
    float yl = y - __uint_as_float(yb & 0xffff0000u); // exact
    asm("cvt.rn.bf16x2.f32 %0, %1, %2;" : "=r"(lo) : "f"(yl), "f"(xl));
}

__global__ __launch_bounds__(256, 2) void gemm_bf16x2_kernel(
    int M, int N, int K,
    const float* __restrict__ A, const float* __restrict__ Bt,
    const float* __restrict__ bias, const float* __restrict__ resid,
    float* __restrict__ C, int mode)
{
    const int BK = 32;
    __shared__ float sA[128][BK + 4];
    __shared__ float sB[128][BK + 4];

    int tid = threadIdx.x;
    int wid = tid >> 5;
    int lane = tid & 31;
    int gid = lane >> 2;      // group id 0..7
    int tig = lane & 3;       // thread in group 0..3
    int wm = (wid >> 1) * 32; // warp m offset 0/32/64/96
    int wn = (wid & 1) * 64;  // warp n offset 0/64
    int m0 = blockIdx.x * 128;
    int n0 = blockIdx.y * 128;

    float acc[2][8][4];
    #pragma unroll
    for (int mf = 0; mf < 2; mf++)
        #pragma unroll
        for (int nf = 0; nf < 8; nf++)
            #pragma unroll
            for (int q = 0; q < 4; q++) acc[mf][nf][q] = 0.f;

    for (int k0 = 0; k0 < K; k0 += BK) {
        // global -> shared: 4 float4 per thread per tile
        #pragma unroll
        for (int i = 0; i < 4; i++) {
            int f = tid + i * 256;
            int row = f >> 3;
            int kq = (f & 7) * 4;
            float4 va = make_float4(0.f, 0.f, 0.f, 0.f);
            if (m0 + row < M) va = *(const float4*)(A + (size_t)(m0 + row) * K + k0 + kq);
            *(float4*)&sA[row][kq] = va;
            float4 vb = make_float4(0.f, 0.f, 0.f, 0.f);
            if (n0 + row < N) vb = *(const float4*)(Bt + (size_t)(n0 + row) * K + k0 + kq);
            *(float4*)&sB[row][kq] = vb;
        }
        __syncthreads();

        #pragma unroll
        for (int ks = 0; ks < 2; ks++) {
            int kk = ks * 16;
            int kx = kk + 2 * tig;
            uint32_t ah[2][4], al[2][4];
            #pragma unroll
            for (int mf = 0; mf < 2; mf++) {
                int r = wm + mf * 16 + gid;
                float2 p0 = *(const float2*)&sA[r][kx];
                float2 p1 = *(const float2*)&sA[r + 8][kx];
                float2 p2 = *(const float2*)&sA[r][kx + 8];
                float2 p3 = *(const float2*)&sA[r + 8][kx + 8];
                split2_bf16(p0.x, p0.y, ah[mf][0], al[mf][0]);
                split2_bf16(p1.x, p1.y, ah[mf][1], al[mf][1]);
                split2_bf16(p2.x, p2.y, ah[mf][2], al[mf][2]);
                split2_bf16(p3.x, p3.y, ah[mf][3], al[mf][3]);
            }
            #pragma unroll
            for (int nf = 0; nf < 8; nf++) {
                int c = wn + nf * 8 + gid;
                float2 q0 = *(const float2*)&sB[c][kx];
                float2 q1 = *(const float2*)&sB[c][kx + 8];
                uint32_t bh[2], bl[2];
                split2_bf16(q0.x, q0.y, bh[0], bl[0]);
                split2_bf16(q1.x, q1.y, bh[1], bl[1]);
                #pragma unroll
                for (int mf = 0; mf < 2; mf++) {
                    mma_bf16(acc[mf][nf], al[mf], bh);
                    mma_bf16(acc[mf][nf], ah[mf], bl);
                    mma_bf16(acc[mf][nf], ah[mf], bh);
                }
            }
        }
        __syncthreads();
    }

    // epilogue
    #pragma unroll
    for (int mf = 0; mf < 2; mf++) {
        int r0 = m0 + wm + mf * 16 + gid;
        int r1 = r0 + 8;
        #pragma unroll
        for (int nf = 0; nf < 8; nf++) {
            int c = n0 + wn + nf * 8 + 2 * tig;
            if (c >= N) continue;
            float bv0 = bias[c];
            float bv1 = bias[c + 1];
            float v00 = acc[mf][nf][0] + bv0;
            float v01 = acc[mf][nf][1] + bv1;
            float v10 = acc[mf][nf][2] + bv0;
            float v11 = acc[mf][nf][3] + bv1;
            if (mode >= 1) {
                v00 = fmaxf(v00, 0.f); v01 = fmaxf(v01, 0.f);
                v10 = fmaxf(v10, 0.f); v11 = fmaxf(v11, 0.f);
            }
            if (r0 < M) {
                if (mode == 2) {
                    v00 += resid[(size_t)r0 * N + c];
                    v01 += resid[(size_t)r0 * N + c + 1];
                }
                *(float2*)(C + (size_t)r0 * N + c) = make_float2(v00, v01);
            }
            if (r1 < M) {
                if (mode == 2) {
                    v10 += resid[(size_t)r1 * N + c];
                    v11 += resid[(size_t)r1 * N + c + 1];
                }
                *(float2*)(C + (size_t)r1 * N + c) = make_float2(v10, v11);
            }
        }
    }
}

// ---------------- driver ----------------
extern "C" void kernel_launch(void* const* d_in, const int* in_sizes, int n_in,
                              void* d_out, int out_size) {
    const float* x      = (const float*)d_in[0];
    const int*   src    = (const int*)  d_in[1];
    const int*   dst    = (const int*)  d_in[2];
    const float* self_w = (const float*)d_in[3];
    const float* ppi_w  = (const float*)d_in[4];
    const float* W_in   = (const float*)d_in[5];
    const float* b_in   = (const float*)d_in[6];
    const float* W1     = (const float*)d_in[7];
    const float* b1     = (const float*)d_in[8];
    const float* W2     = (const float*)d_in[9];
    const float* b2     = (const float*)d_in[10];
    const float* W_out  = (const float*)d_in[11];
    const float* b_out  = (const float*)d_in[12];
    float* out = (float*)d_out;

    float* h     = nullptr; cudaGetSymbolAddress((void**)&h,     g_h);
    float* res   = nullptr; cudaGetSymbolAddress((void**)&res,   g_res);
    float* agg   = nullptr; cudaGetSymbolAddress((void**)&agg,   g_agg);
    float* wtin  = nullptr; cudaGetSymbolAddress((void**)&wtin,  g_wtin);
    float* wt1   = nullptr; cudaGetSymbolAddress((void**)&wt1,   g_wt1);
    float* wt2   = nullptr; cudaGetSymbolAddress((void**)&wt2,   g_wt2);
    float* wtout = nullptr; cudaGetSymbolAddress((void**)&wtout, g_wtout);

    // CSR build
    zero_deg_kernel<<<(NN + 256) / 256, 256>>>();
    hist_kernel<<<(EE + 255) / 256, 256>>>(dst);
    scan_block_kernel<<<NB_SCAN, 1024>>>();
    scan_sums_kernel<<<1, 64>>>();
    finalize_kernel<<<(NN + 255) / 256, 256>>>();
    prime_cursor_kernel<<<(NN + 256) / 256, 256>>>();
    fill_kernel<<<(EE + 255) / 256, 256>>>(src, dst, self_w, ppi_w);

    // weight transposes: W[K][N] -> Wt[N][K]
    {
        dim3 blk(32, 8);
        transpose_kernel<<<dim3((DH + 31) / 32, (DIN + 31) / 32), blk>>>(W_in,  wtin,  DIN, DH);
        transpose_kernel<<<dim3((DH + 31) / 32, (DH + 31) / 32),  blk>>>(W1,    wt1,   DH,  DH);
        transpose_kernel<<<dim3((DH + 31) / 32, (DH + 31) / 32),  blk>>>(W2,    wt2,   DH,  DH);
        transpose_kernel<<<dim3((NL + 31) / 32, (DH + 31) / 32),  blk>>>(W_out, wtout, DH,  NL);
    }

    int mtiles = (NN + 127) / 128;   // 391

    // h = relu(x @ W_in + b_in)
    gemm_bf16x2_kernel<<<dim3(mtiles, 1), 256>>>(NN, DH, DIN, x, wtin, b_in, nullptr, h, 1);

    // two GCN layers
    int agg_blocks = (NN * 32 + 255) / 256;
    aggregate_kernel<<<agg_blocks, 256>>>(h, res, agg);
    gemm_bf16x2_kernel<<<dim3(mtiles, 1), 256>>>(NN, DH, DH, agg, wt1, b1, res, h, 2);
    aggregate_kernel<<<agg_blocks, 256>>>(h, res, agg);
    gemm_bf16x2_kernel<<<dim3(mtiles, 1), 256>>>(NN, DH, DH, agg, wt2, b2, res, h, 2);

    // out = h @ W_out + b_out
    gemm_bf16x2_kernel<<<dim3(mtiles, (NL + 127) / 128), 256>>>(NN, NL, DH, h, wtout, b_out, nullptr, out, 0);
}